// round 14
// baseline (speedup 1.0000x reference)
#include <cuda_runtime.h>
#include <cuda_bf16.h>
#include <cstdint>

#define BB   4
#define HH   16
#define SKK  4096
#define SQQ  4096
#define DD   64
#define NN   32
#define SPLIT_BLK 8
#define SPLIT 16
#define KEYS_PER_BLOCK (SKK / SPLIT_BLK)   // 512
#define CHUNK 32
#define NCHUNK (KEYS_PER_BLOCK / CHUNK)    // 16

typedef unsigned long long u64;

__device__ __forceinline__ float OMEGA() { return 32.0f * 3.14159265358979323846f / 31.0f; }

// Scratch
__device__ float  g_part[SPLIT * 64 * 64 * DD];   // 16.8 MB
__device__ float2 g_ab2[64 * 64 * DD];            // [hb][f][d] {tf32hi, tf32lo} = 2 MB

// ---- packed f32x2 helpers ----
__device__ __forceinline__ u64 pack2(float lo, float hi) {
    u64 r; asm("mov.b64 %0, {%1, %2};" : "=l"(r) : "f"(lo), "f"(hi)); return r;
}
__device__ __forceinline__ void unpack2(u64 v, float& lo, float& hi) {
    asm("mov.b64 {%0, %1}, %2;" : "=f"(lo), "=f"(hi) : "l"(v));
}
__device__ __forceinline__ u64 ffma2(u64 a, u64 b, u64 c) {
    u64 d; asm("fma.rn.f32x2 %0, %1, %2, %3;" : "=l"(d) : "l"(a), "l"(b), "l"(c));
    return d;
}

// ---- tf32 split helper: {hi, lo}, both tf32-formatted f32 ----
__device__ __forceinline__ float2 tf32_split(float x) {
    uint32_t hb_;
    asm("cvt.rna.tf32.f32 %0, %1;" : "=r"(hb_) : "f"(x));
    float hi = __uint_as_float(hb_);
    float lof = x - hi;
    uint32_t lb_;
    asm("cvt.rna.tf32.f32 %0, %1;" : "=r"(lb_) : "f"(lof));
    return make_float2(hi, __uint_as_float(lb_));
}

// ---- m16n8k8 tf32 MMA (classic tensor-core path; valid on compute_103) ----
__device__ __forceinline__ void mma_tf32(float* c,
                                         uint32_t a0, uint32_t a1, uint32_t a2, uint32_t a3,
                                         uint32_t b0, uint32_t b1) {
    asm volatile(
        "mma.sync.aligned.m16n8k8.row.col.f32.tf32.tf32.f32 "
        "{%0,%1,%2,%3}, {%4,%5,%6,%7}, {%8,%9}, {%0,%1,%2,%3};"
        : "+f"(c[0]), "+f"(c[1]), "+f"(c[2]), "+f"(c[3])
        : "r"(a0), "r"(a1), "r"(a2), "r"(a3), "r"(b0), "r"(b1));
}

// ============================================================================
// Kernel 1: partial KV = [cos_k^T V ; sin_k^T V], double-buffered pipeline.
// (unchanged from best round)
// ============================================================================
__global__ __launch_bounds__(256, 3) void kv_partial(const float* __restrict__ key,
                                                     const float* __restrict__ value) {
    const int sblk = blockIdx.x;
    const int hb = blockIdx.y;
    const int h  = hb >> 2;
    const int b  = hb & 3;
    const int tid = threadIdx.x;
    const int ss = tid >> 7;
    const int t  = tid & 127;
    const int n0 = t >> 3;
    const int dg = t & 7;
    const int d0 = dg * 4;

    __shared__ float  sv[2][CHUNK][68];
    __shared__ float2 scs[2][NN][34];

    u64 aC0[4] = {}, aS0[4] = {}, aC1[4] = {}, aS1[4] = {};

    const int kbase = sblk * KEYS_PER_BLOCK;
    const size_t vrow_base = ((size_t)b * SKK) * (HH * DD) + (size_t)h * DD;
    const size_t krow_base = (size_t)b * SKK * HH + h;

    const int vk0 = tid >> 4;
    const int vj0 = tid & 15;
    const int tr  = tid >> 5;
    const int tk  = tid & 31;

    float4 pv0, pv1; float pkey;
    {
        const int kk0 = kbase;
        pv0 = *(reinterpret_cast<const float4*>(
                  value + vrow_base + (size_t)(kk0 + vk0) * (HH * DD)) + vj0);
        pv1 = *(reinterpret_cast<const float4*>(
                  value + vrow_base + (size_t)(kk0 + 16 + vk0) * (HH * DD)) + vj0);
        pkey = key[krow_base + (size_t)(kk0 + tk) * HH];
    }

    for (int c = 0; c < NCHUNK; c++) {
        const int cur = c & 1;

        *reinterpret_cast<float4*>(&sv[cur][vk0][vj0 * 4])      = pv0;
        *reinterpret_cast<float4*>(&sv[cur][16 + vk0][vj0 * 4]) = pv1;
        {
            float base = OMEGA() * pkey;
            float s1, c1; sincosf(base, &s1, &c1);
            float sb, cb; sincosf((float)(4 * tr) * base, &sb, &cb);
            #pragma unroll
            for (int j = 0; j < 4; j++) {
                scs[cur][4 * tr + j][tk] = make_float2(cb, sb);
                float cn = cb * c1 - sb * s1;
                float sn = sb * c1 + cb * s1;
                cb = cn; sb = sn;
            }
        }

        if (c + 1 < NCHUNK) {
            const int kk0 = kbase + (c + 1) * CHUNK;
            pv0 = *(reinterpret_cast<const float4*>(
                      value + vrow_base + (size_t)(kk0 + vk0) * (HH * DD)) + vj0);
            pv1 = *(reinterpret_cast<const float4*>(
                      value + vrow_base + (size_t)(kk0 + 16 + vk0) * (HH * DD)) + vj0);
            pkey = key[krow_base + (size_t)(kk0 + tk) * HH];
        }

        __syncthreads();

        const int kb = ss * 16;
        #pragma unroll
        for (int kk = 0; kk < 16; kk += 2) {
            const int k = kb + kk;
            float4 T0 = *reinterpret_cast<const float4*>(&scs[cur][n0][k]);
            float4 T1 = *reinterpret_cast<const float4*>(&scs[cur][n0 + 16][k]);

            #pragma unroll
            for (int u = 0; u < 2; u++) {
                const float* vrow = &sv[cur][k + u][0];
                ulonglong2 Va = *reinterpret_cast<const ulonglong2*>(vrow + d0);
                ulonglong2 Vb = *reinterpret_cast<const ulonglong2*>(vrow + d0 + 32);
                float cf0 = u ? T0.z : T0.x, sf0 = u ? T0.w : T0.y;
                float cf1 = u ? T1.z : T1.x, sf1 = u ? T1.w : T1.y;
                u64 c0 = pack2(cf0, cf0), s0 = pack2(sf0, sf0);
                u64 c1 = pack2(cf1, cf1), s1 = pack2(sf1, sf1);
                aC0[0] = ffma2(c0, Va.x, aC0[0]); aC0[1] = ffma2(c0, Va.y, aC0[1]);
                aC0[2] = ffma2(c0, Vb.x, aC0[2]); aC0[3] = ffma2(c0, Vb.y, aC0[3]);
                aS0[0] = ffma2(s0, Va.x, aS0[0]); aS0[1] = ffma2(s0, Va.y, aS0[1]);
                aS0[2] = ffma2(s0, Vb.x, aS0[2]); aS0[3] = ffma2(s0, Vb.y, aS0[3]);
                aC1[0] = ffma2(c1, Va.x, aC1[0]); aC1[1] = ffma2(c1, Va.y, aC1[1]);
                aC1[2] = ffma2(c1, Vb.x, aC1[2]); aC1[3] = ffma2(c1, Vb.y, aC1[3]);
                aS1[0] = ffma2(s1, Va.x, aS1[0]); aS1[1] = ffma2(s1, Va.y, aS1[1]);
                aS1[2] = ffma2(s1, Vb.x, aS1[2]); aS1[3] = ffma2(s1, Vb.y, aS1[3]);
            }
        }
    }

    const int sout = sblk * 2 + ss;
    float* base = g_part + (size_t)(sout * 64 + hb) * 64 * DD;
    float o[8];
    u64* accs[4] = {aC0, aC1, aS0, aS1};
    const int frow[4] = {n0, n0 + 16, 32 + n0, 48 + n0};
    #pragma unroll
    for (int g = 0; g < 4; g++) {
        #pragma unroll
        for (int j = 0; j < 4; j++) unpack2(accs[g][j], o[2 * j], o[2 * j + 1]);
        float* p = base + frow[g] * DD + d0;
        *reinterpret_cast<float4*>(p)      = make_float4(o[0], o[1], o[2], o[3]);
        *reinterpret_cast<float4*>(p + 32) = make_float4(o[4], o[5], o[6], o[7]);
    }
}

// ============================================================================
// Kernel 2: reduce split partials, fold amps, emit {tf32hi, tf32lo} AB table
// g_ab2[hb][f][d]  (f = n for A-rows/cos, 32+n for B-rows/sin).
// ============================================================================
__global__ __launch_bounds__(256) void kv_combine(const float* __restrict__ ra,
                                                  const float* __restrict__ ia) {
    const int hb = blockIdx.x;
    const int h  = hb >> 2;
    const int tid = threadIdx.x;

    #pragma unroll
    for (int i = 0; i < 8; i++) {
        int idx = i * 256 + tid;
        int n = idx >> 6, d = idx & 63;
        float sc = 0.f, ss = 0.f;
        #pragma unroll
        for (int s = 0; s < SPLIT; s++) {
            const float* base = g_part + (size_t)(s * 64 + hb) * 64 * DD;
            sc += base[n * DD + d];
            ss += base[(32 + n) * DD + d];
        }
        float r  = ra[h * NN + n];
        float im = ia[h * NN + n];
        float av = r * sc - im * ss;
        float bv = r * ss + im * sc;

        size_t rowb = (size_t)hb * 64 * 64;
        g_ab2[rowb + n * 64 + d]        = tf32_split(av);
        g_ab2[rowb + (32 + n) * 64 + d] = tf32_split(bv);
    }
}

// ============================================================================
// Kernel 3 (tensor cores, m16n8k8 3xTF32):
//   out[64q][64d] = trig[64q][64f] x AB[64f][64d]
// grid (64, 64), block 128 = 4 warps (2x2 over 32q x 32d). Dyn smem 69632 B.
// smem rows pitched 544 B (68 float2) -> conflict-free fragment LDS.64.
// ============================================================================
#define PITCHB 544
#define OFF_B  34816
#define P2_SMEM 69632

__global__ __launch_bounds__(128) void phase2_tc(const float* __restrict__ query,
                                                 float* __restrict__ out) {
    extern __shared__ __align__(16) char smem[];
    const int qt = blockIdx.x, hb = blockIdx.y;
    const int h = hb >> 2, b = hb & 3;
    const int tid = threadIdx.x;
    const int wid = tid >> 5, lane = tid & 31;
    const int qblk = qt * 64;

    // ---- fill B (AB hi/lo) tile: 64 rows x 512 B -> pitched 544 B ----
    {
        const uint4* gb = reinterpret_cast<const uint4*>(g_ab2 + (size_t)hb * 64 * 64);
        #pragma unroll
        for (int i = 0; i < 16; i++) {
            int idx = i * 128 + tid;           // 0..2047
            int row = idx >> 5, j = idx & 31;  // 32 x 16B per row
            *reinterpret_cast<uint4*>(smem + OFF_B + row * PITCHB + j * 16) = gb[idx];
        }
    }

    // ---- trig A tile: 2 threads per q (half 0 = cos rows f=n, half 1 = sin f=32+n) ----
    {
        const int q = tid >> 1, half = tid & 1;
        float qv = query[((size_t)b * SQQ + qblk + q) * HH + h];
        float th = OMEGA() * qv;
        float s1, c1; sincosf(th, &s1, &c1);
        float c2 = c1 * c1 - s1 * s1, s2 = 2.f * c1 * s1;
        float c3 = c2 * c1 - s2 * s1, s3 = s2 * c1 + c2 * s1;
        float c4 = c2 * c2 - s2 * s2, s4 = 2.f * c2 * s2;
        float cc[4] = {1.f, c1, c2, c3};
        float sc[4] = {0.f, s1, s2, s3};
        char* arow = smem + q * PITCHB + half * 32 * 8;
        #pragma unroll
        for (int m = 0; m < 8; m++) {
            #pragma unroll
            for (int g = 0; g < 4; g++) {
                int n = 4 * m + g;
                float x = half ? sc[g] : cc[g];
                *reinterpret_cast<float2*>(arow + n * 8) = tf32_split(x);
                float cn = cc[g] * c4 - sc[g] * s4;
                float sn = sc[g] * c4 + cc[g] * s4;
                cc[g] = cn; sc[g] = sn;
            }
        }
    }
    __syncthreads();

    // ---- warp tile: (wm, wn) over 32q x 32d; 2 m-tiles x 4 n-tiles x 8 k ----
    const int wm = wid & 1, wn = wid >> 1;
    const int g4 = lane >> 2;       // groupID
    const int tg = lane & 3;        // threadID_in_group

    float acc[2][4][4];
    #pragma unroll
    for (int mt = 0; mt < 2; mt++)
        #pragma unroll
        for (int nt = 0; nt < 4; nt++)
            #pragma unroll
            for (int j = 0; j < 4; j++) acc[mt][nt][j] = 0.f;

    #pragma unroll
    for (int ks = 0; ks < 8; ks++) {
        const int f0 = 8 * ks + tg;
        float2 aw[2][4];
        #pragma unroll
        for (int mt = 0; mt < 2; mt++) {
            char* base = smem + (32 * wm + 16 * mt + g4) * PITCHB;
            aw[mt][0] = *reinterpret_cast<float2*>(base + f0 * 8);
            aw[mt][2] = *reinterpret_cast<float2*>(base + (f0 + 4) * 8);
            char* base8 = base + 8 * PITCHB;
            aw[mt][1] = *reinterpret_cast<float2*>(base8 + f0 * 8);
            aw[mt][3] = *reinterpret_cast<float2*>(base8 + (f0 + 4) * 8);
        }
        float2 bw[4][2];
        #pragma unroll
        for (int nt = 0; nt < 4; nt++) {
            char* bb = smem + OFF_B + (8 * ks + tg) * PITCHB
                     + (32 * wn + 8 * nt + g4) * 8;
            bw[nt][0] = *reinterpret_cast<float2*>(bb);
            bw[nt][1] = *reinterpret_cast<float2*>(bb + 4 * PITCHB);
        }
        #pragma unroll
        for (int mt = 0; mt < 2; mt++) {
            uint32_t ah0 = __float_as_uint(aw[mt][0].x), ah1 = __float_as_uint(aw[mt][1].x);
            uint32_t ah2 = __float_as_uint(aw[mt][2].x), ah3 = __float_as_uint(aw[mt][3].x);
            uint32_t al0 = __float_as_uint(aw[mt][0].y), al1 = __float_as_uint(aw[mt][1].y);
            uint32_t al2 = __float_as_uint(aw[mt][2].y), al3 = __float_as_uint(aw[mt][3].y);
            #pragma unroll
            for (int nt = 0; nt < 4; nt++) {
                uint32_t bh0 = __float_as_uint(bw[nt][0].x), bh1 = __float_as_uint(bw[nt][1].x);
                uint32_t bl0 = __float_as_uint(bw[nt][0].y), bl1 = __float_as_uint(bw[nt][1].y);
                mma_tf32(acc[mt][nt], ah0, ah1, ah2, ah3, bh0, bh1);
                mma_tf32(acc[mt][nt], ah0, ah1, ah2, ah3, bl0, bl1);
                mma_tf32(acc[mt][nt], al0, al1, al2, al3, bh0, bh1);
            }
        }
    }

    // ---- epilogue ----
    #pragma unroll
    for (int mt = 0; mt < 2; mt++) {
        const int q = qblk + 32 * wm + 16 * mt + g4;
        #pragma unroll
        for (int nt = 0; nt < 4; nt++) {
            const int d = 32 * wn + 8 * nt + 2 * tg;
            float* p0 = out + (((size_t)b * SQQ + q) * HH + h) * DD + d;
            float* p1 = out + (((size_t)b * SQQ + q + 8) * HH + h) * DD + d;
            *reinterpret_cast<float2*>(p0) = make_float2(acc[mt][nt][0], acc[mt][nt][1]);
            *reinterpret_cast<float2*>(p1) = make_float2(acc[mt][nt][2], acc[mt][nt][3]);
        }
    }
}

// ============================================================================
extern "C" void kernel_launch(void* const* d_in, const int* in_sizes, int n_in,
                              void* d_out, int out_size) {
    const float* key   = (const float*)d_in[0];  // (B, SK, H)
    const float* value = (const float*)d_in[1];  // (B, SK, H*D)
    const float* query = (const float*)d_in[2];  // (B, SQ, H)
    const float* ra    = (const float*)d_in[3];  // (H,1,1,N)
    const float* ia    = (const float*)d_in[4];  // (H,1,1,N)
    float* out = (float*)d_out;                  // (B, SQ, H*D)

    static bool attr_set = false;
    if (!attr_set) {
        cudaFuncSetAttribute(phase2_tc, cudaFuncAttributeMaxDynamicSharedMemorySize,
                             P2_SMEM);
        attr_set = true;
    }

    dim3 g1(SPLIT_BLK, 64);
    kv_partial<<<g1, 256>>>(key, value);
    kv_combine<<<64, 256>>>(ra, ia);
    dim3 g3(SQQ / 64, 64);
    phase2_tc<<<g3, 128, P2_SMEM>>>(query, out);
}